// round 1
// baseline (speedup 1.0000x reference)
#include <cuda_runtime.h>
#include <cstdint>
#include <math_constants.h>

#define N_NODES 100000

// ---------------- device scratch (static globals; no allocation) -------------
__device__ __align__(16) float g_y  [N_NODES * 64];   // (XW)*ns, pre-scatter
__device__ __align__(16) float g_agg[N_NODES * 64];   // scatter accumulator
__device__ __align__(16) float g_h1 [N_NODES * 64];   // layer-1 output
__device__ __align__(16) float g_h2 [N_NODES * 64];   // layer-2 output
__device__ float g_ns[N_NODES];
__device__ float g_nd[N_NODES];
__device__ float g_deg_out[N_NODES];
__device__ float g_deg_in [N_NODES];
__device__ int   g_is64;

// ---------------- index width detection (int64 vs int32) ---------------------
__global__ void detect_idx_kernel(const void* src, int E) {
    const long long* p = (const long long*)src;
    int n = E < 8 ? E : 8;
    int ok = 1;
    for (int i = 0; i < n; i++) {
        long long v = p[i];
        if (v < 0 || v >= (long long)N_NODES) { ok = 0; break; }
    }
    g_is64 = ok;
}

__device__ __forceinline__ int load_idx(const void* p, int i, int is64) {
    return is64 ? (int)((const long long*)p)[i] : ((const int*)p)[i];
}

// ---------------- zero agg (and degrees on first pass) -----------------------
__global__ void zero_agg_deg(int zero_deg) {
    int i = blockIdx.x * blockDim.x + threadIdx.x;
    float4* a = (float4*)g_agg;
    if (i < N_NODES * 64 / 4) a[i] = make_float4(0.f, 0.f, 0.f, 0.f);
    if (zero_deg && i < N_NODES) { g_deg_out[i] = 0.f; g_deg_in[i] = 0.f; }
}

// ---------------- degree accumulation ----------------------------------------
__global__ void degree_kernel(const void* __restrict__ src,
                              const void* __restrict__ dst, int E) {
    int e = blockIdx.x * blockDim.x + threadIdx.x;
    if (e >= E) return;
    int is64 = g_is64;
    atomicAdd(&g_deg_out[load_idx(src, e, is64)], 1.f);
    atomicAdd(&g_deg_in [load_idx(dst, e, is64)], 1.f);
}

__global__ void norm_kernel() {
    int i = blockIdx.x * blockDim.x + threadIdx.x;
    if (i >= N_NODES) return;
    float o = g_deg_out[i], d = g_deg_in[i];
    g_ns[i] = (o > 0.f) ? rsqrtf(o) : 0.f;
    g_nd[i] = (d > 0.f) ? rsqrtf(d) : 0.f;
}

// ---------------- GEMM: Y[n,OUT] = (X[n,IN] @ W[IN,OUT]) * ns[n] -------------
// 256 threads: 32 lanes cover 2 output cols each; 8 row-groups x 4 rows = 32
// rows per block. LDS.128 X loads + LDS.64 W loads -> LDS:FMA ~= 1:4.
template<int IN, int OUT>
__global__ void __launch_bounds__(256) gemm_scale_kernel(
        const float* __restrict__ X, const float* __restrict__ W,
        float* __restrict__ Y, int n) {
    __shared__ float Ws[IN * OUT];
    __shared__ float Xs[32][IN];

    int tid = threadIdx.x;
    for (int i = tid * 4; i < IN * OUT; i += 256 * 4)
        *(float4*)&Ws[i] = *(const float4*)&W[i];

    int row0 = blockIdx.x * 32;
    constexpr int IN4 = IN / 4;
    for (int i = tid; i < 32 * IN4; i += 256) {
        int r = i / IN4, c = i % IN4;
        int gr = row0 + r;
        float4 v = (gr < n) ? *(const float4*)&X[(long)gr * IN + c * 4]
                            : make_float4(0.f, 0.f, 0.f, 0.f);
        *(float4*)&Xs[r][c * 4] = v;
    }
    __syncthreads();

    int lane = tid & 31, rg = tid >> 5;
    int c0 = 2 * lane;
    if (c0 >= OUT) return;

    float acc[4][2] = {};
    #pragma unroll
    for (int k4 = 0; k4 < IN4; k4++) {
        float xv[4][4];
        #pragma unroll
        for (int r = 0; r < 4; r++) {
            float4 t = *(float4*)&Xs[rg * 4 + r][k4 * 4];
            xv[r][0] = t.x; xv[r][1] = t.y; xv[r][2] = t.z; xv[r][3] = t.w;
        }
        #pragma unroll
        for (int kk = 0; kk < 4; kk++) {
            float2 w = *(float2*)&Ws[(k4 * 4 + kk) * OUT + c0];
            #pragma unroll
            for (int r = 0; r < 4; r++) {
                acc[r][0] += xv[r][kk] * w.x;
                acc[r][1] += xv[r][kk] * w.y;
            }
        }
    }
    #pragma unroll
    for (int r = 0; r < 4; r++) {
        int gr = row0 + rg * 4 + r;
        if (gr < n) {
            float s = g_ns[gr];
            *(float2*)&Y[(long)gr * OUT + c0] =
                make_float2(acc[r][0] * s, acc[r][1] * s);
        }
    }
}

// ---------------- scatter: AGG[dst] += Y[src] via red.global.add.v4.f32 ------
template<int OUT>
__global__ void __launch_bounds__(256) scatter_kernel(
        const void* __restrict__ src, const void* __restrict__ dst,
        const float* __restrict__ Y, int E) {
    constexpr int CH = OUT / 4;
    int idx = blockIdx.x * blockDim.x + threadIdx.x;
    int e, c;
    if constexpr ((CH & (CH - 1)) == 0) {
        constexpr int SH = (CH == 16) ? 4 : (CH == 8) ? 3 : (CH == 4) ? 2 : 1;
        e = idx >> SH; c = idx & (CH - 1);
    } else {
        e = idx / CH; c = idx - e * CH;
    }
    if (e >= E) return;
    int is64 = g_is64;
    int s = load_idx(src, e, is64);
    int d = load_idx(dst, e, is64);
    float4 v = __ldg((const float4*)&Y[(long)s * OUT + c * 4]);
    float* p = &g_agg[(long)d * OUT + c * 4];
    asm volatile("red.global.add.v4.f32 [%0], {%1,%2,%3,%4};"
                 :: "l"(p), "f"(v.x), "f"(v.y), "f"(v.z), "f"(v.w)
                 : "memory");
}

// ---------------- epilogue: out = log_softmax(maybe_relu(agg*nd + b)) --------
template<int OUT, bool RELU>
__global__ void __launch_bounds__(256) epilogue_kernel(
        const float* __restrict__ bias, float* __restrict__ Out, int n) {
    int row = blockIdx.x * 8 + (threadIdx.x >> 5);
    if (row >= n) return;
    int lane = threadIdx.x & 31;
    int c0 = 2 * lane;
    bool valid = c0 < OUT;
    float ndv = g_nd[row];
    float v0 = -CUDART_INF_F, v1 = -CUDART_INF_F;
    if (valid) {
        float2 a = *(float2*)&g_agg[(long)row * OUT + c0];
        v0 = a.x * ndv + bias[c0];
        v1 = a.y * ndv + bias[c0 + 1];
        if (RELU) { v0 = fmaxf(v0, 0.f); v1 = fmaxf(v1, 0.f); }
    }
    float m = fmaxf(v0, v1);
    #pragma unroll
    for (int o = 16; o; o >>= 1) m = fmaxf(m, __shfl_xor_sync(0xffffffffu, m, o));
    float s = valid ? (__expf(v0 - m) + __expf(v1 - m)) : 0.f;
    #pragma unroll
    for (int o = 16; o; o >>= 1) s += __shfl_xor_sync(0xffffffffu, s, o);
    float ls = logf(s);
    if (valid)
        *(float2*)&Out[(long)row * OUT + c0] = make_float2(v0 - m - ls, v1 - m - ls);
}

// ---------------- launcher ----------------------------------------------------
extern "C" void kernel_launch(void* const* d_in, const int* in_sizes, int n_in,
                              void* d_out, int out_size) {
    const float* feats = (const float*)d_in[0];
    const void*  src   = d_in[1];
    const void*  dst   = d_in[2];
    const float* W0    = (const float*)d_in[3];
    const float* b0    = (const float*)d_in[4];
    const float* W1    = (const float*)d_in[5];
    const float* b1    = (const float*)d_in[6];
    const float* W2    = (const float*)d_in[7];
    const float* b2    = (const float*)d_in[8];
    float* out = (float*)d_out;
    int E = in_sizes[1];
    int N = N_NODES;

    float *p_h1 = nullptr, *p_h2 = nullptr;
    cudaGetSymbolAddress((void**)&p_h1, g_h1);
    cudaGetSymbolAddress((void**)&p_h2, g_h2);

    const int ZB = (N_NODES * 16 + 255) / 256;      // zero kernel blocks
    const int GB = (N + 31) / 32;                    // gemm blocks
    const int EB = (N + 7) / 8;                      // epilogue blocks

    detect_idx_kernel<<<1, 1>>>(src, E);
    zero_agg_deg<<<ZB, 256>>>(1);
    degree_kernel<<<(E + 255) / 256, 256>>>(src, dst, E);
    norm_kernel<<<(N + 255) / 256, 256>>>();

    // ---- layer 0: 128 -> 64, relu + log_softmax -> g_h1
    gemm_scale_kernel<128, 64><<<GB, 256>>>(feats, W0, g_y, N);
    {
        long total = (long)E * 16;
        scatter_kernel<64><<<(int)((total + 255) / 256), 256>>>(src, dst, g_y, E);
    }
    epilogue_kernel<64, true><<<EB, 256>>>(b0, p_h1, N);
    zero_agg_deg<<<ZB, 256>>>(0);

    // ---- layer 1: 64 -> 64, relu + log_softmax -> g_h2
    gemm_scale_kernel<64, 64><<<GB, 256>>>(p_h1, W1, g_y, N);
    {
        long total = (long)E * 16;
        scatter_kernel<64><<<(int)((total + 255) / 256), 256>>>(src, dst, g_y, E);
    }
    epilogue_kernel<64, true><<<EB, 256>>>(b1, p_h2, N);
    zero_agg_deg<<<ZB, 256>>>(0);

    // ---- layer 2: 64 -> 40, log_softmax -> d_out
    gemm_scale_kernel<64, 40><<<GB, 256>>>(p_h2, W2, g_y, N);
    {
        long total = (long)E * 10;
        scatter_kernel<40><<<(int)((total + 255) / 256), 256>>>(src, dst, g_y, E);
    }
    epilogue_kernel<40, false><<<EB, 256>>>(b2, out, N);
}

// round 2
// speedup vs baseline: 18.9005x; 18.9005x over previous
#include <cuda_runtime.h>
#include <math_constants.h>

#define NN 100000
#define EMAX 1700000
#define SCAN_BS 1024
#define NB ((NN + SCAN_BS - 1) / SCAN_BS)   // 98

// ---------------- device scratch (static globals; no allocation) -------------
__device__ __align__(16) float g_y [NN * 64];   // (XW)*ns, gather source
__device__ __align__(16) float g_h1[NN * 64];   // layer-1 output
__device__ __align__(16) float g_h2[NN * 64];   // layer-2 output
__device__ float g_ns[NN];
__device__ float g_nd[NN];
__device__ int g_cnt_out[NN];
__device__ int g_cnt_in [NN];
__device__ int g_cursor [NN];
__device__ int g_rowptr [NN + 1];
__device__ int g_blocksum[NB];
__device__ int g_esrc[EMAX];                    // src indices sorted by dst
__device__ int g_is64;

// ---------------- index width detection (int64 vs int32) ---------------------
__global__ void detect_idx_kernel(const void* src, int E) {
    const long long* p = (const long long*)src;
    int n = E < 8 ? E : 8;
    int ok = 1;
    for (int i = 0; i < n; i++) {
        long long v = p[i];
        if (v < 0 || v >= (long long)NN) { ok = 0; break; }
    }
    g_is64 = ok;
}

__device__ __forceinline__ int load_idx(const void* p, int i, int is64) {
    return is64 ? (int)((const long long*)p)[i] : ((const int*)p)[i];
}

// ---------------- zero histograms + cursors ----------------------------------
__global__ void zero_counts() {
    int i = blockIdx.x * blockDim.x + threadIdx.x;
    if (i < NN) { g_cnt_out[i] = 0; g_cnt_in[i] = 0; g_cursor[i] = 0; }
}

// ---------------- degree histograms (int atomics, cheap) ----------------------
__global__ void hist_kernel(const void* __restrict__ src,
                            const void* __restrict__ dst, int E) {
    int e = blockIdx.x * blockDim.x + threadIdx.x;
    if (e >= E) return;
    int is64 = g_is64;
    atomicAdd(&g_cnt_out[load_idx(src, e, is64)], 1);
    atomicAdd(&g_cnt_in [load_idx(dst, e, is64)], 1);
}

// ---------------- exclusive scan of cnt_in -> rowptr (3 kernels) --------------
__global__ void __launch_bounds__(SCAN_BS) scan1_kernel() {
    __shared__ int sh[SCAN_BS];
    int tid = threadIdx.x;
    int i = blockIdx.x * SCAN_BS + tid;
    int v = (i < NN) ? g_cnt_in[i] : 0;
    sh[tid] = v;
    __syncthreads();
    #pragma unroll
    for (int off = 1; off < SCAN_BS; off <<= 1) {
        int t = (tid >= off) ? sh[tid - off] : 0;
        __syncthreads();
        sh[tid] += t;
        __syncthreads();
    }
    if (i < NN) g_rowptr[i] = sh[tid] - v;          // exclusive (per-block)
    if (tid == SCAN_BS - 1) g_blocksum[blockIdx.x] = sh[tid];
}

__global__ void scan2_kernel() {
    // tiny: serial exclusive scan of 98 block sums
    int running = 0;
    for (int b = 0; b < NB; b++) {
        int t = g_blocksum[b];
        g_blocksum[b] = running;
        running += t;
    }
    g_rowptr[NN] = running;                          // == E
}

__global__ void __launch_bounds__(SCAN_BS) scan3_kernel() {
    int i = blockIdx.x * SCAN_BS + threadIdx.x;
    if (i >= NN) return;
    g_rowptr[i] += g_blocksum[blockIdx.x];
    int o = g_cnt_out[i], d = g_cnt_in[i];
    g_ns[i] = (o > 0) ? rsqrtf((float)o) : 0.f;
    g_nd[i] = (d > 0) ? rsqrtf((float)d) : 0.f;
}

// ---------------- edge placement: CSR by dst ----------------------------------
__global__ void place_kernel(const void* __restrict__ src,
                             const void* __restrict__ dst, int E) {
    int e = blockIdx.x * blockDim.x + threadIdx.x;
    if (e >= E) return;
    int is64 = g_is64;
    int s = load_idx(src, e, is64);
    int d = load_idx(dst, e, is64);
    int pos = g_rowptr[d] + atomicAdd(&g_cursor[d], 1);
    g_esrc[pos] = s;
}

// ---------------- GEMM: Y[n,OUT] = (X[n,IN] @ W[IN,OUT]) * ns[n] -------------
template<int IN, int OUT>
__global__ void __launch_bounds__(256) gemm_scale_kernel(
        const float* __restrict__ X, const float* __restrict__ W,
        float* __restrict__ Y) {
    __shared__ float Ws[IN * OUT];
    __shared__ float Xs[32][IN];

    int tid = threadIdx.x;
    for (int i = tid * 4; i < IN * OUT; i += 256 * 4)
        *(float4*)&Ws[i] = *(const float4*)&W[i];

    int row0 = blockIdx.x * 32;
    constexpr int IN4 = IN / 4;
    for (int i = tid; i < 32 * IN4; i += 256) {
        int r = i / IN4, c = i % IN4;
        int gr = row0 + r;
        float4 v = (gr < NN) ? *(const float4*)&X[(long)gr * IN + c * 4]
                             : make_float4(0.f, 0.f, 0.f, 0.f);
        *(float4*)&Xs[r][c * 4] = v;
    }
    __syncthreads();

    int lane = tid & 31, rg = tid >> 5;
    int c0 = 2 * lane;
    if (c0 >= OUT) return;

    float acc[4][2] = {};
    #pragma unroll
    for (int k4 = 0; k4 < IN4; k4++) {
        float xv[4][4];
        #pragma unroll
        for (int r = 0; r < 4; r++) {
            float4 t = *(float4*)&Xs[rg * 4 + r][k4 * 4];
            xv[r][0] = t.x; xv[r][1] = t.y; xv[r][2] = t.z; xv[r][3] = t.w;
        }
        #pragma unroll
        for (int kk = 0; kk < 4; kk++) {
            float2 w = *(float2*)&Ws[(k4 * 4 + kk) * OUT + c0];
            #pragma unroll
            for (int r = 0; r < 4; r++) {
                acc[r][0] += xv[r][kk] * w.x;
                acc[r][1] += xv[r][kk] * w.y;
            }
        }
    }
    #pragma unroll
    for (int r = 0; r < 4; r++) {
        int gr = row0 + rg * 4 + r;
        if (gr < NN) {
            float s = g_ns[gr];
            *(float2*)&Y[(long)gr * OUT + c0] =
                make_float2(acc[r][0] * s, acc[r][1] * s);
        }
    }
}

// ---------------- fused SpMM-gather + epilogue --------------------------------
// One warp per dst row: gather Y[src] over CSR neighbor list, accumulate in
// registers (2 cols/lane), then agg*nd + bias (+relu) + log_softmax.
template<int OUT, bool RELU>
__global__ void __launch_bounds__(256) spmm_epi_kernel(
        const float* __restrict__ Y, const float* __restrict__ bias,
        float* __restrict__ Out) {
    int row = blockIdx.x * 8 + (threadIdx.x >> 5);
    if (row >= NN) return;
    int lane = threadIdx.x & 31;
    int c0 = 2 * lane;
    bool valid = c0 < OUT;

    int beg = g_rowptr[row], end = g_rowptr[row + 1];
    float a0 = 0.f, a1 = 0.f, b0_ = 0.f, b1_ = 0.f;

    for (int base = beg; base < end; base += 32) {
        int rem = end - base; if (rem > 32) rem = 32;
        int my = (lane < rem) ? g_esrc[base + lane] : 0;
        int j = 0;
        // 4-way unroll: 4 independent L2 gathers in flight per warp
        for (; j + 4 <= rem; j += 4) {
            int s0 = __shfl_sync(0xffffffffu, my, j);
            int s1 = __shfl_sync(0xffffffffu, my, j + 1);
            int s2 = __shfl_sync(0xffffffffu, my, j + 2);
            int s3 = __shfl_sync(0xffffffffu, my, j + 3);
            if (valid) {
                float2 v0 = __ldg((const float2*)&Y[(long)s0 * OUT + c0]);
                float2 v1 = __ldg((const float2*)&Y[(long)s1 * OUT + c0]);
                float2 v2 = __ldg((const float2*)&Y[(long)s2 * OUT + c0]);
                float2 v3 = __ldg((const float2*)&Y[(long)s3 * OUT + c0]);
                a0 += v0.x; a1 += v0.y;
                b0_ += v1.x; b1_ += v1.y;
                a0 += v2.x; a1 += v2.y;
                b0_ += v3.x; b1_ += v3.y;
            }
        }
        for (; j < rem; j++) {
            int s = __shfl_sync(0xffffffffu, my, j);
            if (valid) {
                float2 v = __ldg((const float2*)&Y[(long)s * OUT + c0]);
                a0 += v.x; a1 += v.y;
            }
        }
    }
    a0 += b0_; a1 += b1_;

    float ndv = g_nd[row];
    float v0 = -CUDART_INF_F, v1 = -CUDART_INF_F;
    if (valid) {
        v0 = a0 * ndv + bias[c0];
        v1 = a1 * ndv + bias[c0 + 1];
        if (RELU) { v0 = fmaxf(v0, 0.f); v1 = fmaxf(v1, 0.f); }
    }
    float m = fmaxf(v0, v1);
    #pragma unroll
    for (int o = 16; o; o >>= 1) m = fmaxf(m, __shfl_xor_sync(0xffffffffu, m, o));
    float s = valid ? (__expf(v0 - m) + __expf(v1 - m)) : 0.f;
    #pragma unroll
    for (int o = 16; o; o >>= 1) s += __shfl_xor_sync(0xffffffffu, s, o);
    float ls = logf(s);
    if (valid)
        *(float2*)&Out[(long)row * OUT + c0] = make_float2(v0 - m - ls, v1 - m - ls);
}

// ---------------- launcher ----------------------------------------------------
extern "C" void kernel_launch(void* const* d_in, const int* in_sizes, int n_in,
                              void* d_out, int out_size) {
    const float* feats = (const float*)d_in[0];
    const void*  src   = d_in[1];
    const void*  dst   = d_in[2];
    const float* W0    = (const float*)d_in[3];
    const float* b0    = (const float*)d_in[4];
    const float* W1    = (const float*)d_in[5];
    const float* b1    = (const float*)d_in[6];
    const float* W2    = (const float*)d_in[7];
    const float* b2    = (const float*)d_in[8];
    float* out = (float*)d_out;
    int E = in_sizes[1];

    float *p_y = nullptr, *p_h1 = nullptr, *p_h2 = nullptr;
    cudaGetSymbolAddress((void**)&p_y,  g_y);
    cudaGetSymbolAddress((void**)&p_h1, g_h1);
    cudaGetSymbolAddress((void**)&p_h2, g_h2);

    const int GB = (NN + 31) / 32;    // gemm blocks
    const int SB = (NN + 7) / 8;      // spmm/epilogue blocks (warp per row)
    const int EB = (E + 255) / 256;   // per-edge blocks

    // ---- CSR build (each call; graph-capturable, int atomics only)
    detect_idx_kernel<<<1, 1>>>(src, E);
    zero_counts<<<(NN + 255) / 256, 256>>>();
    hist_kernel<<<EB, 256>>>(src, dst, E);
    scan1_kernel<<<NB, SCAN_BS>>>();
    scan2_kernel<<<1, 1>>>();
    scan3_kernel<<<NB, SCAN_BS>>>();
    place_kernel<<<EB, 256>>>(src, dst, E);

    // ---- layer 0: 128 -> 64, relu + log_softmax -> g_h1
    gemm_scale_kernel<128, 64><<<GB, 256>>>(feats, W0, p_y);
    spmm_epi_kernel<64, true><<<SB, 256>>>(p_y, b0, p_h1);

    // ---- layer 1: 64 -> 64, relu + log_softmax -> g_h2
    gemm_scale_kernel<64, 64><<<GB, 256>>>(p_h1, W1, p_y);
    spmm_epi_kernel<64, true><<<SB, 256>>>(p_y, b1, p_h2);

    // ---- layer 2: 64 -> 40, log_softmax -> d_out
    gemm_scale_kernel<64, 40><<<GB, 256>>>(p_h2, W2, p_y);
    spmm_epi_kernel<40, false><<<SB, 256>>>(p_y, b2, out);
}